// round 15
// baseline (speedup 1.0000x reference)
#include <cuda_runtime.h>
#include <cuda_fp16.h>
#include <math.h>
#include <stdint.h>

#define BSZ 32
#define CCH 128
#define HH  32
#define WW  32
#define HWP (HH*WW)
#define LL  (CCH*HWP)
#define NTOT (BSZ*LL)
#define MMH 5
#define LAMREG 1e-4f
#define TOLV 1e-5f

// ---------------- device state ----------------
__device__ float g_Fp[6][NTOT];        // F history, physical buffers (k mod 6)
__device__ float g_G[MMH][NTOT];       // G[j] = F[j] - X[j]
__device__ float g_X[NTOT];            // current iterate
__device__ float g_Row[50 * BSZ * 8];  // versioned Gram rows: [k][b][j]
__device__ float g_Rden[50];           // versioned residual denominators
__device__ uint4 g_Wf0[72 * 256];      // A fragments: fp16
__device__ unsigned g_barCnt;
__device__ unsigned g_barGen;
__device__ int g_tileCtr[64];          // per-pass work counters
__device__ int g_rowFlag[BSZ * HH];    // versioned row-ready flags (value == kpass)

#define NROWIT 256                     // row items (4 rows each)
#define NTILE  1160                    // 888 full rows + 272 half-rows
#define NQ     (NROWIT + NTILE)

// ---------------- helpers ----------------
__device__ __forceinline__ uint32_t smem_u32(const void* p) {
    uint32_t a;
    asm("{ .reg .u64 t; cvta.to.shared.u64 t, %1; cvt.u32.u64 %0, t; }" : "=r"(a) : "l"(p));
    return a;
}
__device__ __forceinline__ uint32_t pk2h(float a, float b) {
    __half2 t = __floats2half2_rn(a, b);
    return *reinterpret_cast<uint32_t*>(&t);
}
__device__ __forceinline__ float warpReduceSum(float v) {
#pragma unroll
    for (int o = 16; o > 0; o >>= 1) v += __shfl_xor_sync(0xFFFFFFFF, v, o);
    return v;
}

#define LDMX4(r0, r1, r2, r3, addr) \
    asm volatile("ldmatrix.sync.aligned.m8n8.x4.shared.b16 {%0,%1,%2,%3}, [%4];" \
        : "=r"(r0), "=r"(r1), "=r"(r2), "=r"(r3) : "r"(addr))

#define MMA(d, a, b0_, b1_) \
    asm volatile("mma.sync.aligned.m16n8k16.row.col.f32.f16.f16.f32 " \
        "{%0,%1,%2,%3}, {%4,%5,%6,%7}, {%8,%9}, {%0,%1,%2,%3};" \
        : "+f"((d)[0]), "+f"((d)[1]), "+f"((d)[2]), "+f"((d)[3]) \
        : "r"((a).x), "r"((a).y), "r"((a).z), "r"((a).w), "r"(b0_), "r"(b1_))

// ---------------- smem layout (bytes); sPre ALIASES the B tile area ----------------
// Bsm: [r 3][xi 34][ci 128 pad 136] fp16
#define BSM_ROWB   272
#define BSM_RSTR   (34 * BSM_ROWB)        // 9248
#define BSM_BYTES  (3 * BSM_RSTR)         // 27744
#define PMAX_B     BSM_BYTES
#define PINV_B     (PMAX_B + 128)
#define PRED_B     (PINV_B + 128)
#define SMEM_TOTAL (PRED_B + 256)         // 28256

// ---------------- grid barrier ----------------
__device__ __forceinline__ void grid_sync(int nblk) {
    __syncthreads();
    if (threadIdx.x == 0) {
        __threadfence();
        unsigned gen = *(volatile unsigned*)&g_barGen;
        if (atomicAdd(&g_barCnt, 1) == (unsigned)(nblk - 1)) {
            g_barCnt = 0;
            __threadfence();
            atomicAdd(&g_barGen, 1);
        } else {
            while (*(volatile unsigned*)&g_barGen == gen) {}
            __threadfence();
        }
    }
    __syncthreads();
}

// ---------------- Anderson solve from smem-staged Gram rows ----------------
__device__ void solve_smem(int b, int ks, const int* u, const float* sRowS, float* alpha5) {
    int n = ks < MMH ? ks : MMH;
    float S[MMH][MMH];
    for (int i = 0; i < n; i++)
        for (int j = 0; j <= i; j++) {
            float v = (u[i] >= u[j]) ? sRowS[i * 160 + b * 5 + j]
                                     : sRowS[j * 160 + b * 5 + i];
            S[i][j] = v; S[j][i] = v;
        }
    float A[6][6], rv[6];
    A[0][0] = 0.f;
    for (int j = 0; j < MMH; j++) {
        float a = (j < n) ? 1.f : 0.f;
        A[0][j + 1] = a; A[j + 1][0] = a;
    }
    for (int i = 0; i < MMH; i++)
        for (int j = 0; j < MMH; j++) {
            float v;
            if (i < n && j < n) v = S[i][j] + ((i == j) ? LAMREG : 0.f);
            else                v = (i == j) ? 1.f : 0.f;
            A[i + 1][j + 1] = v;
        }
    for (int i = 0; i < 6; i++) rv[i] = 0.f;
    rv[0] = 1.f;
    for (int c = 0; c < 6; c++) {
        int p = c; float mx = fabsf(A[c][c]);
        for (int r = c + 1; r < 6; r++) { float t = fabsf(A[r][c]); if (t > mx) { mx = t; p = r; } }
        if (p != c) {
            for (int q = c; q < 6; q++) { float t = A[c][q]; A[c][q] = A[p][q]; A[p][q] = t; }
            float t = rv[c]; rv[c] = rv[p]; rv[p] = t;
        }
        float inv = 1.f / A[c][c];
        for (int r = c + 1; r < 6; r++) {
            float f = A[r][c] * inv;
            if (f != 0.f) {
                for (int q = c + 1; q < 6; q++) A[r][q] -= f * A[c][q];
                rv[r] -= f * rv[c];
            }
        }
    }
    float xs[6];
    for (int c = 5; c >= 0; c--) {
        float t = rv[c];
        for (int q = c + 1; q < 6; q++) t -= A[c][q] * xs[q];
        xs[c] = t / A[c][c];
    }
    for (int j = 0; j < MMH; j++) alpha5[j] = (j < n) ? xs[j + 1] : 0.f;
}

// simple staging: v = mask ? x : z  ->  fp16 pairs
__device__ __forceinline__ void stage_unit(int m, const float* xsrc, const float* zsrc,
                                           char* dst0, int nci) {
#pragma unroll 4
    for (int ci = 0; ci < nci; ci += 2) {
        size_t o0 = (size_t)ci * HWP, o1 = o0 + (size_t)HWP;
        float va = m ? xsrc[o0] : zsrc[o0];
        float vb = m ? xsrc[o1] : zsrc[o1];
        *(uint32_t*)(dst0 + ci * 2) = pk2h(va, vb);
    }
}

// ---------------- one f-evaluation pass (row items + hybrid conv tiles) ----------------
__device__ __noinline__ void eval_pass(int slot, int n, int nact, int do_res, int pin, int pw,
                                       int p0, int p1, int p2, int p3, int p4,
                                       int kpass, const float* sAlpha,
                                       const float* __restrict__ xg,
                                       const int* __restrict__ maskg,
                                       const float* __restrict__ bias,
                                       float* sm) {
    const uint32_t smb = smem_u32(sm);
    const int tid = threadIdx.x;
    const int w = tid >> 5, lane = tid & 31;
    const float* zin = (n == 0 && pin >= 0) ? g_Fp[pin] : g_X;
    float* fout = g_Fp[pw];
    float* gout = g_G[slot];
    float* pMax = (float*)((char*)sm + PMAX_B);
    float* pInv = (float*)((char*)sm + PINV_B);
    float* pRed = (float*)((char*)sm + PRED_B);
    __shared__ int stile;

    const int fragidx = w * 32 + lane;
    const int mi = lane >> 3;
    const int khalf = mi & 1;
    const int qrow = mi >> 1;

    for (;;) {
        if (tid == 0) stile = atomicAdd(&g_tileCtr[kpass], 1);
        __syncthreads();
        int item = stile;
        if (item >= NQ) break;

        // ============ ROW ITEM: compute xnew for 4 rows, publish flags ============
        if (item < NROWIT) {
            if (n > 0) {
                int row = item * 4 + (w >> 1);
                int bb = row >> 5, yy = row & 31;
                int cih = (w & 1) * 64;
                float a0 = sAlpha[bb * 5 + 0], a1 = sAlpha[bb * 5 + 1], a2 = sAlpha[bb * 5 + 2],
                      a3 = sAlpha[bb * 5 + 3], a4 = sAlpha[bb * 5 + 4];
                size_t base = ((size_t)(bb * CCH + cih) * HH + yy) * WW + lane;
                const float* f0 = g_Fp[p0] + base;
                const float* f1 = g_Fp[p1] + base;
                const float* f2 = g_Fp[p2] + base;
                const float* f3 = g_Fp[p3] + base;
                const float* f4 = g_Fp[p4] + base;
                float* zw = g_X + base;
#pragma unroll 4
                for (int ci = 0; ci < 64; ci++) {
                    size_t o = (size_t)ci * HWP;
                    float xa = a0 * f0[o];
                    if (n > 1) xa = fmaf(a1, f1[o], xa);
                    if (n > 2) xa = fmaf(a2, f2[o], xa);
                    if (n > 3) xa = fmaf(a3, f3[o], xa);
                    if (n > 4) xa = fmaf(a4, f4[o], xa);
                    zw[o] = xa;
                }
                __syncthreads();
                __threadfence();
                if (tid < 4) *(volatile int*)&g_rowFlag[item * 4 + tid] = kpass;
            }
            continue;
        }

        int tile = item - NROWIT;
        int rid, xh;
        if (tile < 888) { rid = tile; xh = -1; }
        else { int h = tile - 888; rid = 888 + (h >> 1); xh = h & 1; }
        const int b = rid >> 5;
        const int y = rid & 31;

        // wait for the 3 input rows (n>0 only)
        if (n > 0) {
            if (tid < 3) {
                int ry = y - 1 + tid;
                if (ry >= 0 && ry < HH) {
                    volatile int* fl = &g_rowFlag[b * HH + ry];
                    while (*fl != kpass) {}
                    __threadfence();
                }
            }
            __syncthreads();
        }

        if (xh < 0) {
            // ================= FULL-ROW TILE =================
            for (int i = tid; i < 6 * 68; i += 256) {
                int word = i % 68;
                int rr = i / 68;
                int r = rr >> 1; int xi = (rr & 1) ? 33 : 0;
                ((uint32_t*)((char*)sm + r * BSM_RSTR + xi * BSM_ROWB))[word] = 0;
            }
            for (int t = w; t < 24; t += 8) {
                int r = t >> 3, cig = t & 7;
                int r_img = y + r - 1;
                char* dst0 = (char*)sm + r * BSM_RSTR + (lane + 1) * BSM_ROWB + cig * 32;
                if (r_img >= 0 && r_img < HH) {
                    int m = maskg[(b * HH + r_img) * WW + lane];
                    size_t bi = ((size_t)(b * CCH + cig * 16) * HH + r_img) * WW + lane;
                    stage_unit(m, xg + bi, zin + bi, dst0, 16);
                } else {
#pragma unroll
                    for (int ci = 0; ci < 16; ci += 2)
                        *(uint32_t*)(dst0 + ci * 2) = 0;
                }
            }
            __syncthreads();

            // conv: n=32, single fp16 A, double-buffered over (p, cig)
            float acc[16];
#pragma unroll
            for (int i = 0; i < 16; i++) acc[i] = 0.f;

            const uint4* pA0 = g_Wf0 + fragidx;
            uint4 A0 = pA0[0];

            uint32_t abase[2];
#pragma unroll
            for (int p = 0; p < 2; p++)
                abase[p] = smb + (uint32_t)(((p * 2 + qrow) * 8 + (lane & 7)) * BSM_ROWB + khalf * 16);

            uint32_t Bb[2][4];
            LDMX4(Bb[0][0], Bb[0][1], Bb[0][2], Bb[0][3], abase[0]);

            uint32_t kb = 0;
#pragma unroll 1
            for (int ky = 0; ky < 3; ky++) {
#pragma unroll 1
                for (int kxc = 0; kxc < 3; kxc++) {
                    uint32_t kbn = (kxc < 2) ? kb + BSM_ROWB : (uint32_t)((ky + 1) * BSM_RSTR);
#pragma unroll
                    for (int cig = 0; cig < 8; cig++) {
                        bool last = (ky == 2) && (kxc == 2) && (cig == 7);
                        uint4 nA0;
                        if (!last) { nA0 = pA0[256]; }
                        pA0 += 256;
                        uint32_t koff = kb + (uint32_t)(cig * 32);
                        uint32_t nkoff = (cig < 7) ? (koff + 32) : kbn;
#pragma unroll
                        for (int p = 0; p < 2; p++) {
                            uint32_t* cb = Bb[p];
                            uint32_t* nb = Bb[p ^ 1];
                            if (p == 0) {
                                LDMX4(nb[0], nb[1], nb[2], nb[3], abase[1] + koff);
                            } else if (!last) {
                                LDMX4(nb[0], nb[1], nb[2], nb[3], abase[0] + nkoff);
                            }
                            float* d0 = &acc[8 * p];
                            float* d1 = d0 + 4;
                            MMA(d0, A0, cb[0], cb[1]);
                            MMA(d1, A0, cb[2], cb[3]);
                        }
                        if (!last) { A0 = nA0; }
                    }
                    kb = kbn;
                }
            }
            __syncthreads();   // Bsm dead; sPre aliases

            float* sPre = sm;
#pragma unroll
            for (int half = 0; half < 2; half++) {
                int co = w * 16 + (lane >> 2) + half * 8;
                float bco = bias[co];
                const float* zr = zin + ((b * CCH + co) * HH + y) * WW;
                float* sp = sPre + co * 33;
#pragma unroll
                for (int nt = 0; nt < 4; nt++) {
                    int x = nt * 8 + (lane & 3) * 2;
                    float v0 = acc[nt * 4 + half * 2 + 0];
                    float v1 = acc[nt * 4 + half * 2 + 1];
                    sp[x]     = 0.1f * zr[x]     + 0.9f * (v0 + bco);
                    sp[x + 1] = 0.1f * zr[x + 1] + 0.9f * (v1 + bco);
                }
            }
            __syncthreads();

            for (int xx = w; xx < WW; xx += 8) {
                float m = -1e30f;
#pragma unroll
                for (int i = 0; i < 4; i++) m = fmaxf(m, sPre[(lane + 32 * i) * 33 + xx]);
#pragma unroll
                for (int o = 16; o > 0; o >>= 1) m = fmaxf(m, __shfl_xor_sync(0xFFFFFFFF, m, o));
                float ss = 0.f;
#pragma unroll
                for (int i = 0; i < 4; i++) ss += __expf(sPre[(lane + 32 * i) * 33 + xx] - m);
                ss = warpReduceSum(ss);
                if (lane == 0) { pMax[xx] = m; pInv[xx] = 1.0f / ss; }
            }
            __syncthreads();

            const int x = lane;
            float dots[MMH] = {0.f, 0.f, 0.f, 0.f, 0.f};
            float resd = 0.f;
            float mx = pMax[x], inv = pInv[x];
            for (int c = w; c < CCH; c += 8) {
                int idx = ((b * CCH + c) * HH + y) * WW + x;
                float val = __expf(sPre[c * 33 + x] - mx) * inv;
                fout[idx] = val;
                float gs = val - zin[idx];
                gout[idx] = gs;
#pragma unroll
                for (int j = 0; j < MMH; j++) {
                    if (j < nact) {
                        float gj = (j == slot) ? gs : g_G[j][idx];
                        dots[j] = fmaf(gs, gj, dots[j]);
                    }
                }
                resd = fmaf(val, val, resd);
            }
#pragma unroll
            for (int j = 0; j < MMH; j++) {
                float v = warpReduceSum(dots[j]);
                if (lane == 0) pRed[w * 6 + j] = v;
            }
            {
                float v = warpReduceSum(resd);
                if (lane == 0) pRed[w * 6 + 5] = v;
            }
            __syncthreads();
            if (w == 0 && lane < 6) {
                bool act = (lane < nact) || (lane == 5 && do_res);
                if (act) {
                    float t = 0.f;
#pragma unroll
                    for (int i = 0; i < 8; i++) t += pRed[i * 6 + lane];
                    if (lane < MMH) atomicAdd(&g_Row[(kpass * BSZ + b) * 8 + lane], t);
                    else            atomicAdd(&g_Rden[kpass], t);
                }
            }
        } else {
            // ================= HALF-ROW TILE =================
            for (int t = w; t < 48; t += 8) {
                int r = t >> 4, cig = t & 15;
                int r_img = y + r - 1;
                if (lane < 18) {
                    int gx = xh * 16 + lane - 1;
                    char* dst0 = (char*)sm + r * BSM_RSTR + (xh * 16 + lane) * BSM_ROWB + cig * 16;
                    bool valid = (r_img >= 0) && (r_img < HH) && (gx >= 0) && (gx < WW);
                    if (valid) {
                        int m = maskg[(b * HH + r_img) * WW + gx];
                        size_t bi = ((size_t)(b * CCH + cig * 8) * HH + r_img) * WW + gx;
                        stage_unit(m, xg + bi, zin + bi, dst0, 8);
                    } else {
#pragma unroll
                        for (int ci = 0; ci < 8; ci += 2)
                            *(uint32_t*)(dst0 + ci * 2) = 0;
                    }
                }
            }
            __syncthreads();

            float acc[8];
#pragma unroll
            for (int i = 0; i < 8; i++) acc[i] = 0.f;

            const uint4* pA0 = g_Wf0 + fragidx;
            uint4 A0 = pA0[0];

            const uint32_t base = smb + (uint32_t)((xh * 16 + qrow * 8 + (lane & 7)) * BSM_ROWB + khalf * 16);

            uint32_t Bb[2][4];
            LDMX4(Bb[0][0], Bb[0][1], Bb[0][2], Bb[0][3], base);

            uint32_t kb = 0;
            int bufi = 0;
#pragma unroll 1
            for (int ky = 0; ky < 3; ky++) {
#pragma unroll 1
                for (int kxc = 0; kxc < 3; kxc++) {
                    uint32_t kbn = (kxc < 2) ? kb + BSM_ROWB : (uint32_t)((ky + 1) * BSM_RSTR);
#pragma unroll
                    for (int cig = 0; cig < 8; cig++) {
                        bool last = (ky == 2) && (kxc == 2) && (cig == 7);
                        uint4 nA0;
                        if (!last) { nA0 = pA0[256]; }
                        pA0 += 256;
                        uint32_t noff = (cig < 7) ? (kb + (uint32_t)(cig + 1) * 32) : kbn;
                        uint32_t* cb = Bb[bufi];
                        uint32_t* nb = Bb[bufi ^ 1];
                        if (!last) {
                            LDMX4(nb[0], nb[1], nb[2], nb[3], base + noff);
                        }
                        float* d0 = &acc[0];
                        float* d1 = &acc[4];
                        MMA(d0, A0, cb[0], cb[1]);
                        MMA(d1, A0, cb[2], cb[3]);
                        bufi ^= 1;
                        if (!last) { A0 = nA0; }
                    }
                    kb = kbn;
                }
            }
            __syncthreads();

            float* sPre = sm;   // [co][17]
#pragma unroll
            for (int half = 0; half < 2; half++) {
                int co = w * 16 + (lane >> 2) + half * 8;
                float bco = bias[co];
                const float* zr = zin + ((b * CCH + co) * HH + y) * WW + xh * 16;
                float* sp = sPre + co * 17;
#pragma unroll
                for (int nt = 0; nt < 2; nt++) {
                    int x = nt * 8 + (lane & 3) * 2;
                    float v0 = acc[nt * 4 + half * 2 + 0];
                    float v1 = acc[nt * 4 + half * 2 + 1];
                    sp[x]     = 0.1f * zr[x]     + 0.9f * (v0 + bco);
                    sp[x + 1] = 0.1f * zr[x + 1] + 0.9f * (v1 + bco);
                }
            }
            __syncthreads();

            for (int xx = w; xx < 16; xx += 8) {
                float m = -1e30f;
#pragma unroll
                for (int i = 0; i < 4; i++) m = fmaxf(m, sPre[(lane + 32 * i) * 17 + xx]);
#pragma unroll
                for (int o = 16; o > 0; o >>= 1) m = fmaxf(m, __shfl_xor_sync(0xFFFFFFFF, m, o));
                float ss = 0.f;
#pragma unroll
                for (int i = 0; i < 4; i++) ss += __expf(sPre[(lane + 32 * i) * 17 + xx] - m);
                ss = warpReduceSum(ss);
                if (lane == 0) { pMax[xx] = m; pInv[xx] = 1.0f / ss; }
            }
            __syncthreads();

            const int xl = lane & 15;
            const int ch = lane >> 4;
            float dots[MMH] = {0.f, 0.f, 0.f, 0.f, 0.f};
            float resd = 0.f;
            float mx = pMax[xl], inv = pInv[xl];
#pragma unroll 2
            for (int j = 0; j < 8; j++) {
                int c = 2 * w + ch + 16 * j;
                int idx = ((b * CCH + c) * HH + y) * WW + xh * 16 + xl;
                float val = __expf(sPre[c * 17 + xl] - mx) * inv;
                fout[idx] = val;
                float gs = val - zin[idx];
                gout[idx] = gs;
#pragma unroll
                for (int jj = 0; jj < MMH; jj++) {
                    if (jj < nact) {
                        float gj = (jj == slot) ? gs : g_G[jj][idx];
                        dots[jj] = fmaf(gs, gj, dots[jj]);
                    }
                }
                resd = fmaf(val, val, resd);
            }
#pragma unroll
            for (int j = 0; j < MMH; j++) {
                float v = warpReduceSum(dots[j]);
                if (lane == 0) pRed[w * 6 + j] = v;
            }
            {
                float v = warpReduceSum(resd);
                if (lane == 0) pRed[w * 6 + 5] = v;
            }
            __syncthreads();
            if (w == 0 && lane < 6) {
                bool act = (lane < nact) || (lane == 5 && do_res);
                if (act) {
                    float t = 0.f;
#pragma unroll
                    for (int i = 0; i < 8; i++) t += pRed[i * 6 + lane];
                    if (lane < MMH) atomicAdd(&g_Row[(kpass * BSZ + b) * 8 + lane], t);
                    else            atomicAdd(&g_Rden[kpass], t);
                }
            }
        }
    }
}

// ---------------- the whole algorithm as ONE persistent kernel ----------------
__global__ void __launch_bounds__(256, 3)
mon_persistent(int nblk,
               const float* __restrict__ xg, const int* __restrict__ maskg,
               const float* __restrict__ bias, const float* __restrict__ W,
               float* __restrict__ out) {
    extern __shared__ float sm[];
    __shared__ float sAlpha[BSZ * 5];
    const int tid = threadIdx.x;
    const int gt = blockIdx.x * 256 + tid;

    // ---- init ----
    if (gt < 72 * 256) {
        int s = gt >> 8, rem = gt & 255, w = rem >> 5, l = rem & 31;
        int ky = s / 24, kx = (s / 8) % 3, cig = s & 7;
        int m0 = w * 16 + (l >> 2);
        int k0 = cig * 16 + (l & 3) * 2;
        uint32_t big[4];
#pragma unroll
        for (int jc = 0; jc < 2; jc++)
#pragma unroll
            for (int jr = 0; jr < 2; jr++) {
                int reg = jc * 2 + jr;
                int co = m0 + jr * 8;
                int ci = k0 + jc * 8;
                float wa = W[((co * CCH + ci) * 3 + ky) * 3 + kx];
                float wb = W[((co * CCH + ci + 1) * 3 + ky) * 3 + kx];
                big[reg] = pk2h(wa, wb);
            }
        g_Wf0[gt] = make_uint4(big[0], big[1], big[2], big[3]);
    }
    {
        const float v = 1.0f / 128.0f;
        float4 vv = make_float4(v, v, v, v);
        for (int i4 = gt; i4 < NTOT / 4; i4 += nblk * 256) ((float4*)g_X)[i4] = vv;
    }
    if (gt < 50 * BSZ * 8) g_Row[gt] = 0.f;
    else if (gt < 50 * BSZ * 8 + 50) g_Rden[gt - 50 * BSZ * 8] = 0.f;
    else if (gt < 50 * BSZ * 8 + 50 + 64) g_tileCtr[gt - 50 * BSZ * 8 - 50] = 0;
    if (gt < BSZ * HH) g_rowFlag[gt] = -1;
    grid_sync(nblk);

    // ---- k=0, k=1 ----
    eval_pass(0, 0, 1, 0, -1, 0, 0, 0, 0, 0, 0, 0, sAlpha, xg, maskg, bias, sm);
    grid_sync(nblk);
    eval_pass(1, 0, 2, 0, 0, 1, 0, 0, 0, 0, 0, 1, sAlpha, xg, maskg, bias, sm);
    grid_sync(nblk);
    // alpha(2)
    {
        int u[5];
#pragma unroll
        for (int j = 0; j < 5; j++) u[j] = 1 - ((1 - j) % 5);
        for (int t = tid; t < 2 * 160; t += 256) {
            int i = t / 160, r = t % 160;
            sm[t] = g_Row[(u[i] * BSZ + r / 5) * 8 + (r % 5)];
        }
        __syncthreads();
        if (tid < BSZ) solve_smem(tid, 2, u, sm, &sAlpha[tid * 5]);
        __syncthreads();
    }

    // ---- main loop: ONE grid_sync per iteration; smem consensus ----
    int outslot = 1;
    for (int k = 2; k < 50; k++) {
        int s = k % MMH;
        int n = (k < MMH) ? k : MMH;
        int nact = (k + 1 < MMH) ? (k + 1) : MMH;
        int pw = k % 6;
        int pj[5];
#pragma unroll
        for (int j = 0; j < 5; j++) {
            int kj = k - 1 - ((k - 1 - j) % 5);
            pj[j] = kj % 6;
        }
        eval_pass(s, n, nact, 1, -1, pw, pj[0], pj[1], pj[2], pj[3], pj[4],
                  k, sAlpha, xg, maskg, bias, sm);
        grid_sync(nblk);

        int ks = k + 1;
        int nn = (ks < MMH) ? ks : MMH;
        int u[5];
#pragma unroll
        for (int j = 0; j < 5; j++) u[j] = k - ((k - j) % 5);
        for (int t = tid; t < nn * 160; t += 256) {
            int i = t / 160, r = t % 160;
            sm[t] = g_Row[(u[i] * BSZ + r / 5) * 8 + (r % 5)];
        }
        __syncthreads();

        int i0 = s;
        float rn = 0.f;
        for (int bb = 0; bb < BSZ; bb++) rn += sm[i0 * 160 + bb * 5 + i0];
        float res = sqrtf(rn) / (1e-5f + sqrtf(g_Rden[k]));
        outslot = pw;
        if (res < TOLV || ks >= 50) break;
        if (tid < BSZ) solve_smem(tid, ks, u, sm, &sAlpha[tid * 5]);
        __syncthreads();
    }

    // ---- final: out = F[outslot] ----
    {
        const float4* src = (const float4*)g_Fp[outslot];
        for (int i4 = gt; i4 < NTOT / 4; i4 += nblk * 256) ((float4*)out)[i4] = src[i4];
    }
}

// ---------------- host ----------------
extern "C" void kernel_launch(void* const* d_in, const int* in_sizes, int n_in,
                              void* d_out, int out_size) {
    const float* x = nullptr; const float* W = nullptr;
    const float* bias = nullptr; const int* mask = nullptr;
    for (int i = 0; i < n_in; i++) {
        switch (in_sizes[i]) {
            case 4194304: x    = (const float*)d_in[i]; break;
            case 147456:  W    = (const float*)d_in[i]; break;
            case 128:     bias = (const float*)d_in[i]; break;
            case 32768:   mask = (const int*)d_in[i];   break;
        }
    }
    float* out = (float*)d_out;

    int smcount = 0;
    if (cudaDeviceGetAttribute(&smcount, cudaDevAttrMultiProcessorCount, 0) != cudaSuccess
        || smcount <= 0) smcount = 148;
    int nblk = smcount * 3;   // 3 blocks/SM

    cudaFuncSetAttribute(mon_persistent, cudaFuncAttributeMaxDynamicSharedMemorySize, SMEM_TOTAL);
    mon_persistent<<<nblk, 256, SMEM_TOTAL>>>(nblk, x, mask, bias, W, out);
    (void)out_size;
}

// round 16
// speedup vs baseline: 1.1434x; 1.1434x over previous
#include <cuda_runtime.h>
#include <cuda_fp16.h>
#include <math.h>
#include <stdint.h>

#define BSZ 32
#define CCH 128
#define HH  32
#define WW  32
#define HWP (HH*WW)
#define LL  (CCH*HWP)
#define NTOT (BSZ*LL)
#define MMH 5
#define LAMREG 1e-4f
#define TOLV 1e-5f

// ---------------- device state ----------------
__device__ float g_Fp[6][NTOT];        // F history, physical buffers (k mod 6)
__device__ float g_G[MMH][NTOT];       // G[j] = F[j] - X[j]
__device__ float g_X[NTOT];            // current iterate
__device__ float g_Row[50 * BSZ * 8];  // versioned Gram rows: [k][b][j]
__device__ float g_Rden[50];           // versioned residual denominators
__device__ uint4 g_Wf0[72 * 256];      // A fragments: fp16
__device__ unsigned g_barCnt;
__device__ unsigned g_barGen;
__device__ int g_tileCtr[64];          // per-pass tile counters

#define NTILE 1160                     // 888 full rows + 272 half-rows (rows 888..1023)

// ---------------- helpers ----------------
__device__ __forceinline__ uint32_t smem_u32(const void* p) {
    uint32_t a;
    asm("{ .reg .u64 t; cvta.to.shared.u64 t, %1; cvt.u32.u64 %0, t; }" : "=r"(a) : "l"(p));
    return a;
}
__device__ __forceinline__ uint32_t pk2h(float a, float b) {
    __half2 t = __floats2half2_rn(a, b);
    return *reinterpret_cast<uint32_t*>(&t);
}
__device__ __forceinline__ float warpReduceSum(float v) {
#pragma unroll
    for (int o = 16; o > 0; o >>= 1) v += __shfl_xor_sync(0xFFFFFFFF, v, o);
    return v;
}

#define LDMX4(r0, r1, r2, r3, addr) \
    asm volatile("ldmatrix.sync.aligned.m8n8.x4.shared.b16 {%0,%1,%2,%3}, [%4];" \
        : "=r"(r0), "=r"(r1), "=r"(r2), "=r"(r3) : "r"(addr))

#define MMA(d, a, b0_, b1_) \
    asm volatile("mma.sync.aligned.m16n8k16.row.col.f32.f16.f16.f32 " \
        "{%0,%1,%2,%3}, {%4,%5,%6,%7}, {%8,%9}, {%0,%1,%2,%3};" \
        : "+f"((d)[0]), "+f"((d)[1]), "+f"((d)[2]), "+f"((d)[3]) \
        : "r"((a).x), "r"((a).y), "r"((a).z), "r"((a).w), "r"(b0_), "r"(b1_))

// ---------------- smem layout (bytes); sPre ALIASES the B tile area ----------------
// Bsm: [r 3][xi 34][ci 128 pad 136] fp16
#define BSM_ROWB   272
#define BSM_RSTR   (34 * BSM_ROWB)        // 9248
#define BSM_BYTES  (3 * BSM_RSTR)         // 27744
#define PMAX_B     BSM_BYTES
#define PINV_B     (PMAX_B + 128)
#define PRED_B     (PINV_B + 128)
#define SMEM_TOTAL (PRED_B + 256)         // 28256

// ---------------- grid barrier ----------------
__device__ __forceinline__ void grid_sync(int nblk) {
    __syncthreads();
    if (threadIdx.x == 0) {
        __threadfence();
        unsigned gen = *(volatile unsigned*)&g_barGen;
        if (atomicAdd(&g_barCnt, 1) == (unsigned)(nblk - 1)) {
            g_barCnt = 0;
            __threadfence();
            atomicAdd(&g_barGen, 1);
        } else {
            while (*(volatile unsigned*)&g_barGen == gen) {}
            __threadfence();
        }
    }
    __syncthreads();
}

// ---------------- Anderson solve from smem-staged Gram rows ----------------
__device__ void solve_smem(int b, int ks, const int* u, const float* sRowS, float* alpha5) {
    int n = ks < MMH ? ks : MMH;
    float S[MMH][MMH];
    for (int i = 0; i < n; i++)
        for (int j = 0; j <= i; j++) {
            float v = (u[i] >= u[j]) ? sRowS[i * 160 + b * 5 + j]
                                     : sRowS[j * 160 + b * 5 + i];
            S[i][j] = v; S[j][i] = v;
        }
    float A[6][6], rv[6];
    A[0][0] = 0.f;
    for (int j = 0; j < MMH; j++) {
        float a = (j < n) ? 1.f : 0.f;
        A[0][j + 1] = a; A[j + 1][0] = a;
    }
    for (int i = 0; i < MMH; i++)
        for (int j = 0; j < MMH; j++) {
            float v;
            if (i < n && j < n) v = S[i][j] + ((i == j) ? LAMREG : 0.f);
            else                v = (i == j) ? 1.f : 0.f;
            A[i + 1][j + 1] = v;
        }
    for (int i = 0; i < 6; i++) rv[i] = 0.f;
    rv[0] = 1.f;
    for (int c = 0; c < 6; c++) {
        int p = c; float mx = fabsf(A[c][c]);
        for (int r = c + 1; r < 6; r++) { float t = fabsf(A[r][c]); if (t > mx) { mx = t; p = r; } }
        if (p != c) {
            for (int q = c; q < 6; q++) { float t = A[c][q]; A[c][q] = A[p][q]; A[p][q] = t; }
            float t = rv[c]; rv[c] = rv[p]; rv[p] = t;
        }
        float inv = 1.f / A[c][c];
        for (int r = c + 1; r < 6; r++) {
            float f = A[r][c] * inv;
            if (f != 0.f) {
                for (int q = c + 1; q < 6; q++) A[r][q] -= f * A[c][q];
                rv[r] -= f * rv[c];
            }
        }
    }
    float xs[6];
    for (int c = 5; c >= 0; c--) {
        float t = rv[c];
        for (int q = c + 1; q < 6; q++) t -= A[c][q] * xs[q];
        xs[c] = t / A[c][c];
    }
    for (int j = 0; j < MMH; j++) alpha5[j] = (j < n) ? xs[j + 1] : 0.f;
}

// staging of one (r, ci-group of nci) unit into the B layout (fp16), fused x-update
__device__ __forceinline__ void stage_unit(
    int n, int m, size_t bi, bool center,
    const float* xsrc, const float* zsrc,
    const float* f0, const float* f1, const float* f2, const float* f3, const float* f4,
    float a0, float a1, float a2, float a3, float a4, float* zw,
    char* dst0, int nci) {
    if (n > 0) {
        for (int ci = 0; ci < nci; ci += 2) {
            size_t o0 = (size_t)ci * HWP, o1 = o0 + (size_t)HWP;
            float xa = a0 * f0[o0], xb = a0 * f0[o1];
            if (n > 1) { xa = fmaf(a1, f1[o0], xa); xb = fmaf(a1, f1[o1], xb); }
            if (n > 2) { xa = fmaf(a2, f2[o0], xa); xb = fmaf(a2, f2[o1], xb); }
            if (n > 3) { xa = fmaf(a3, f3[o0], xa); xb = fmaf(a3, f3[o1], xb); }
            if (n > 4) { xa = fmaf(a4, f4[o0], xa); xb = fmaf(a4, f4[o1], xb); }
            if (center) { zw[o0] = xa; zw[o1] = xb; }
            float va = m ? xsrc[o0] : xa;
            float vb = m ? xsrc[o1] : xb;
            *(uint32_t*)(dst0 + ci * 2) = pk2h(va, vb);
        }
    } else {
        for (int ci = 0; ci < nci; ci += 2) {
            size_t o0 = (size_t)ci * HWP, o1 = o0 + (size_t)HWP;
            float va = m ? xsrc[o0] : zsrc[o0];
            float vb = m ? xsrc[o1] : zsrc[o1];
            *(uint32_t*)(dst0 + ci * 2) = pk2h(va, vb);
        }
    }
}

// ---------------- one f-evaluation pass (hybrid tiles) ----------------
__device__ __noinline__ void eval_pass(int slot, int n, int nact, int do_res, int pin, int pw,
                                       int p0, int p1, int p2, int p3, int p4,
                                       int kpass, const float* sAlpha,
                                       const float* __restrict__ xg,
                                       const int* __restrict__ maskg,
                                       const float* __restrict__ bias,
                                       float* sm) {
    const uint32_t smb = smem_u32(sm);
    const int tid = threadIdx.x;
    const int w = tid >> 5, lane = tid & 31;
    const float* zin = (n == 0 && pin >= 0) ? g_Fp[pin] : g_X;
    float* fout = g_Fp[pw];
    float* gout = g_G[slot];
    float* pMax = (float*)((char*)sm + PMAX_B);
    float* pInv = (float*)((char*)sm + PINV_B);
    float* pRed = (float*)((char*)sm + PRED_B);
    __shared__ int stile;

    const int fragidx = w * 32 + lane;
    const int mi = lane >> 3;
    const int khalf = mi & 1;
    const int qrow = mi >> 1;

    for (;;) {
        if (tid == 0) stile = atomicAdd(&g_tileCtr[kpass], 1);
        __syncthreads();
        int tile = stile;
        if (tile >= NTILE) break;
        int rid, xh;
        if (tile < 888) { rid = tile; xh = -1; }
        else { int h = tile - 888; rid = 888 + (h >> 1); xh = h & 1; }
        const int b = rid >> 5;
        const int y = rid & 31;

        if (xh < 0) {
            // ================= FULL-ROW TILE =================
            for (int i = tid; i < 6 * 68; i += 256) {
                int word = i % 68;
                int rr = i / 68;
                int r = rr >> 1; int xi = (rr & 1) ? 33 : 0;
                ((uint32_t*)((char*)sm + r * BSM_RSTR + xi * BSM_ROWB))[word] = 0;
            }
            for (int t = w; t < 24; t += 8) {
                int r = t >> 3, cig = t & 7;
                int r_img = y + r - 1;
                char* dst0 = (char*)sm + r * BSM_RSTR + (lane + 1) * BSM_ROWB + cig * 32;
                if (r_img >= 0 && r_img < HH) {
                    int m = maskg[(b * HH + r_img) * WW + lane];
                    size_t bi = ((size_t)(b * CCH + cig * 16) * HH + r_img) * WW + lane;
                    stage_unit(n, m, bi, (r == 1),
                               xg + bi, zin + bi,
                               g_Fp[p0] + bi, g_Fp[p1] + bi, g_Fp[p2] + bi, g_Fp[p3] + bi, g_Fp[p4] + bi,
                               sAlpha[b * 5 + 0], sAlpha[b * 5 + 1], sAlpha[b * 5 + 2],
                               sAlpha[b * 5 + 3], sAlpha[b * 5 + 4], g_X + bi,
                               dst0, 16);
                } else {
#pragma unroll
                    for (int ci = 0; ci < 16; ci += 2)
                        *(uint32_t*)(dst0 + ci * 2) = 0;
                }
            }
            __syncthreads();

            // conv: n=32, single fp16 A (no A prefetch buffer), B double-buffered
            float acc[16];
#pragma unroll
            for (int i = 0; i < 16; i++) acc[i] = 0.f;

            const uint4* pA0 = g_Wf0 + fragidx;

            uint32_t abase[2];
#pragma unroll
            for (int p = 0; p < 2; p++)
                abase[p] = smb + (uint32_t)(((p * 2 + qrow) * 8 + (lane & 7)) * BSM_ROWB + khalf * 16);

            uint32_t Bb[2][4];
            LDMX4(Bb[0][0], Bb[0][1], Bb[0][2], Bb[0][3], abase[0]);

            uint32_t kb = 0;
#pragma unroll 1
            for (int ky = 0; ky < 3; ky++) {
#pragma unroll 1
                for (int kxc = 0; kxc < 3; kxc++) {
                    uint32_t kbn = (kxc < 2) ? kb + BSM_ROWB : (uint32_t)((ky + 1) * BSM_RSTR);
#pragma unroll
                    for (int cig = 0; cig < 8; cig++) {
                        bool last = (ky == 2) && (kxc == 2) && (cig == 7);
                        uint4 A0 = *pA0;
                        pA0 += 256;
                        uint32_t koff = kb + (uint32_t)(cig * 32);
                        uint32_t nkoff = (cig < 7) ? (koff + 32) : kbn;
#pragma unroll
                        for (int p = 0; p < 2; p++) {
                            uint32_t* cb = Bb[p];
                            uint32_t* nb = Bb[p ^ 1];
                            if (p == 0) {
                                LDMX4(nb[0], nb[1], nb[2], nb[3], abase[1] + koff);
                            } else if (!last) {
                                LDMX4(nb[0], nb[1], nb[2], nb[3], abase[0] + nkoff);
                            }
                            float* d0 = &acc[8 * p];
                            float* d1 = d0 + 4;
                            MMA(d0, A0, cb[0], cb[1]);
                            MMA(d1, A0, cb[2], cb[3]);
                        }
                    }
                    kb = kbn;
                }
            }
            __syncthreads();   // Bsm dead; sPre aliases

            float* sPre = sm;
#pragma unroll
            for (int half = 0; half < 2; half++) {
                int co = w * 16 + (lane >> 2) + half * 8;
                float bco = bias[co];
                const float* zr = zin + ((b * CCH + co) * HH + y) * WW;
                float* sp = sPre + co * 33;
#pragma unroll
                for (int nt = 0; nt < 4; nt++) {
                    int x = nt * 8 + (lane & 3) * 2;
                    float v0 = acc[nt * 4 + half * 2 + 0];
                    float v1 = acc[nt * 4 + half * 2 + 1];
                    sp[x]     = 0.1f * zr[x]     + 0.9f * (v0 + bco);
                    sp[x + 1] = 0.1f * zr[x + 1] + 0.9f * (v1 + bco);
                }
            }
            __syncthreads();

            for (int xx = w; xx < WW; xx += 8) {
                float m = -1e30f;
#pragma unroll
                for (int i = 0; i < 4; i++) m = fmaxf(m, sPre[(lane + 32 * i) * 33 + xx]);
#pragma unroll
                for (int o = 16; o > 0; o >>= 1) m = fmaxf(m, __shfl_xor_sync(0xFFFFFFFF, m, o));
                float ss = 0.f;
#pragma unroll
                for (int i = 0; i < 4; i++) ss += __expf(sPre[(lane + 32 * i) * 33 + xx] - m);
                ss = warpReduceSum(ss);
                if (lane == 0) { pMax[xx] = m; pInv[xx] = 1.0f / ss; }
            }
            __syncthreads();

            const int x = lane;
            float dots[MMH] = {0.f, 0.f, 0.f, 0.f, 0.f};
            float resd = 0.f;
            float mx = pMax[x], inv = pInv[x];
            for (int c = w; c < CCH; c += 8) {
                int idx = ((b * CCH + c) * HH + y) * WW + x;
                float val = __expf(sPre[c * 33 + x] - mx) * inv;
                fout[idx] = val;
                float gs = val - zin[idx];
                gout[idx] = gs;
#pragma unroll
                for (int j = 0; j < MMH; j++) {
                    if (j < nact) {
                        float gj = (j == slot) ? gs : g_G[j][idx];
                        dots[j] = fmaf(gs, gj, dots[j]);
                    }
                }
                resd = fmaf(val, val, resd);
            }
#pragma unroll
            for (int j = 0; j < MMH; j++) {
                float v = warpReduceSum(dots[j]);
                if (lane == 0) pRed[w * 6 + j] = v;
            }
            {
                float v = warpReduceSum(resd);
                if (lane == 0) pRed[w * 6 + 5] = v;
            }
            __syncthreads();
            if (w == 0 && lane < 6) {
                bool act = (lane < nact) || (lane == 5 && do_res);
                if (act) {
                    float t = 0.f;
#pragma unroll
                    for (int i = 0; i < 8; i++) t += pRed[i * 6 + lane];
                    if (lane < MMH) atomicAdd(&g_Row[(kpass * BSZ + b) * 8 + lane], t);
                    else            atomicAdd(&g_Rden[kpass], t);
                }
            }
        } else {
            // ================= HALF-ROW TILE =================
            for (int t = w; t < 48; t += 8) {
                int r = t >> 4, cig = t & 15;
                int r_img = y + r - 1;
                if (lane < 18) {
                    int gx = xh * 16 + lane - 1;
                    char* dst0 = (char*)sm + r * BSM_RSTR + (xh * 16 + lane) * BSM_ROWB + cig * 16;
                    bool valid = (r_img >= 0) && (r_img < HH) && (gx >= 0) && (gx < WW);
                    if (valid) {
                        int m = maskg[(b * HH + r_img) * WW + gx];
                        size_t bi = ((size_t)(b * CCH + cig * 8) * HH + r_img) * WW + gx;
                        bool center = (r == 1) && (lane >= 1) && (lane <= 16);
                        stage_unit(n, m, bi, center,
                                   xg + bi, zin + bi,
                                   g_Fp[p0] + bi, g_Fp[p1] + bi, g_Fp[p2] + bi, g_Fp[p3] + bi, g_Fp[p4] + bi,
                                   sAlpha[b * 5 + 0], sAlpha[b * 5 + 1], sAlpha[b * 5 + 2],
                                   sAlpha[b * 5 + 3], sAlpha[b * 5 + 4], g_X + bi,
                                   dst0, 8);
                    } else {
#pragma unroll
                        for (int ci = 0; ci < 8; ci += 2)
                            *(uint32_t*)(dst0 + ci * 2) = 0;
                    }
                }
            }
            __syncthreads();

            float acc[8];
#pragma unroll
            for (int i = 0; i < 8; i++) acc[i] = 0.f;

            const uint4* pA0 = g_Wf0 + fragidx;

            const uint32_t base = smb + (uint32_t)((xh * 16 + qrow * 8 + (lane & 7)) * BSM_ROWB + khalf * 16);

            uint32_t Bb[2][4];
            LDMX4(Bb[0][0], Bb[0][1], Bb[0][2], Bb[0][3], base);

            uint32_t kb = 0;
            int bufi = 0;
#pragma unroll 1
            for (int ky = 0; ky < 3; ky++) {
#pragma unroll 1
                for (int kxc = 0; kxc < 3; kxc++) {
                    uint32_t kbn = (kxc < 2) ? kb + BSM_ROWB : (uint32_t)((ky + 1) * BSM_RSTR);
#pragma unroll
                    for (int cig = 0; cig < 8; cig++) {
                        bool last = (ky == 2) && (kxc == 2) && (cig == 7);
                        uint4 A0 = *pA0;
                        pA0 += 256;
                        uint32_t noff = (cig < 7) ? (kb + (uint32_t)(cig + 1) * 32) : kbn;
                        uint32_t* cb = Bb[bufi];
                        uint32_t* nb = Bb[bufi ^ 1];
                        if (!last) {
                            LDMX4(nb[0], nb[1], nb[2], nb[3], base + noff);
                        }
                        float* d0 = &acc[0];
                        float* d1 = &acc[4];
                        MMA(d0, A0, cb[0], cb[1]);
                        MMA(d1, A0, cb[2], cb[3]);
                        bufi ^= 1;
                    }
                    kb = kbn;
                }
            }
            __syncthreads();

            float* sPre = sm;   // [co][17]
#pragma unroll
            for (int half = 0; half < 2; half++) {
                int co = w * 16 + (lane >> 2) + half * 8;
                float bco = bias[co];
                const float* zr = zin + ((b * CCH + co) * HH + y) * WW + xh * 16;
                float* sp = sPre + co * 17;
#pragma unroll
                for (int nt = 0; nt < 2; nt++) {
                    int x = nt * 8 + (lane & 3) * 2;
                    float v0 = acc[nt * 4 + half * 2 + 0];
                    float v1 = acc[nt * 4 + half * 2 + 1];
                    sp[x]     = 0.1f * zr[x]     + 0.9f * (v0 + bco);
                    sp[x + 1] = 0.1f * zr[x + 1] + 0.9f * (v1 + bco);
                }
            }
            __syncthreads();

            for (int xx = w; xx < 16; xx += 8) {
                float m = -1e30f;
#pragma unroll
                for (int i = 0; i < 4; i++) m = fmaxf(m, sPre[(lane + 32 * i) * 17 + xx]);
#pragma unroll
                for (int o = 16; o > 0; o >>= 1) m = fmaxf(m, __shfl_xor_sync(0xFFFFFFFF, m, o));
                float ss = 0.f;
#pragma unroll
                for (int i = 0; i < 4; i++) ss += __expf(sPre[(lane + 32 * i) * 17 + xx] - m);
                ss = warpReduceSum(ss);
                if (lane == 0) { pMax[xx] = m; pInv[xx] = 1.0f / ss; }
            }
            __syncthreads();

            const int xl = lane & 15;
            const int ch = lane >> 4;
            float dots[MMH] = {0.f, 0.f, 0.f, 0.f, 0.f};
            float resd = 0.f;
            float mx = pMax[xl], inv = pInv[xl];
#pragma unroll 2
            for (int j = 0; j < 8; j++) {
                int c = 2 * w + ch + 16 * j;
                int idx = ((b * CCH + c) * HH + y) * WW + xh * 16 + xl;
                float val = __expf(sPre[c * 17 + xl] - mx) * inv;
                fout[idx] = val;
                float gs = val - zin[idx];
                gout[idx] = gs;
#pragma unroll
                for (int jj = 0; jj < MMH; jj++) {
                    if (jj < nact) {
                        float gj = (jj == slot) ? gs : g_G[jj][idx];
                        dots[jj] = fmaf(gs, gj, dots[jj]);
                    }
                }
                resd = fmaf(val, val, resd);
            }
#pragma unroll
            for (int j = 0; j < MMH; j++) {
                float v = warpReduceSum(dots[j]);
                if (lane == 0) pRed[w * 6 + j] = v;
            }
            {
                float v = warpReduceSum(resd);
                if (lane == 0) pRed[w * 6 + 5] = v;
            }
            __syncthreads();
            if (w == 0 && lane < 6) {
                bool act = (lane < nact) || (lane == 5 && do_res);
                if (act) {
                    float t = 0.f;
#pragma unroll
                    for (int i = 0; i < 8; i++) t += pRed[i * 6 + lane];
                    if (lane < MMH) atomicAdd(&g_Row[(kpass * BSZ + b) * 8 + lane], t);
                    else            atomicAdd(&g_Rden[kpass], t);
                }
            }
        }
    }
}

// ---------------- the whole algorithm as ONE persistent kernel ----------------
__global__ void __launch_bounds__(256, 4)
mon_persistent(int nblk,
               const float* __restrict__ xg, const int* __restrict__ maskg,
               const float* __restrict__ bias, const float* __restrict__ W,
               float* __restrict__ out) {
    extern __shared__ float sm[];
    __shared__ float sAlpha[BSZ * 5];
    const int tid = threadIdx.x;
    const int gt = blockIdx.x * 256 + tid;

    // ---- init: fp16 weight fragments, z0, versioned state ----
    if (gt < 72 * 256) {
        int s = gt >> 8, rem = gt & 255, w = rem >> 5, l = rem & 31;
        int ky = s / 24, kx = (s / 8) % 3, cig = s & 7;
        int m0 = w * 16 + (l >> 2);
        int k0 = cig * 16 + (l & 3) * 2;
        uint32_t big[4];
#pragma unroll
        for (int jc = 0; jc < 2; jc++)
#pragma unroll
            for (int jr = 0; jr < 2; jr++) {
                int reg = jc * 2 + jr;
                int co = m0 + jr * 8;
                int ci = k0 + jc * 8;
                float wa = W[((co * CCH + ci) * 3 + ky) * 3 + kx];
                float wb = W[((co * CCH + ci + 1) * 3 + ky) * 3 + kx];
                big[reg] = pk2h(wa, wb);
            }
        g_Wf0[gt] = make_uint4(big[0], big[1], big[2], big[3]);
    }
    {
        const float v = 1.0f / 128.0f;
        float4 vv = make_float4(v, v, v, v);
        for (int i4 = gt; i4 < NTOT / 4; i4 += nblk * 256) ((float4*)g_X)[i4] = vv;
    }
    if (gt < 50 * BSZ * 8) g_Row[gt] = 0.f;
    else if (gt < 50 * BSZ * 8 + 50) g_Rden[gt - 50 * BSZ * 8] = 0.f;
    else if (gt < 50 * BSZ * 8 + 50 + 64) g_tileCtr[gt - 50 * BSZ * 8 - 50] = 0;
    grid_sync(nblk);

    // ---- k=0, k=1 ----
    eval_pass(0, 0, 1, 0, -1, 0, 0, 0, 0, 0, 0, 0, sAlpha, xg, maskg, bias, sm);
    grid_sync(nblk);
    eval_pass(1, 0, 2, 0, 0, 1, 0, 0, 0, 0, 0, 1, sAlpha, xg, maskg, bias, sm);
    grid_sync(nblk);
    // alpha(2)
    {
        int u[5];
#pragma unroll
        for (int j = 0; j < 5; j++) u[j] = 1 - ((1 - j) % 5);
        for (int t = tid; t < 2 * 160; t += 256) {
            int i = t / 160, r = t % 160;
            sm[t] = g_Row[(u[i] * BSZ + r / 5) * 8 + (r % 5)];
        }
        __syncthreads();
        if (tid < BSZ) solve_smem(tid, 2, u, sm, &sAlpha[tid * 5]);
        __syncthreads();
    }

    // ---- main loop: ONE grid_sync per iteration; smem consensus ----
    int outslot = 1;
    for (int k = 2; k < 50; k++) {
        int s = k % MMH;
        int n = (k < MMH) ? k : MMH;
        int nact = (k + 1 < MMH) ? (k + 1) : MMH;
        int pw = k % 6;
        int pj[5];
#pragma unroll
        for (int j = 0; j < 5; j++) {
            int kj = k - 1 - ((k - 1 - j) % 5);
            pj[j] = kj % 6;
        }
        eval_pass(s, n, nact, 1, -1, pw, pj[0], pj[1], pj[2], pj[3], pj[4],
                  k, sAlpha, xg, maskg, bias, sm);
        grid_sync(nblk);

        int ks = k + 1;
        int nn = (ks < MMH) ? ks : MMH;
        int u[5];
#pragma unroll
        for (int j = 0; j < 5; j++) u[j] = k - ((k - j) % 5);
        for (int t = tid; t < nn * 160; t += 256) {
            int i = t / 160, r = t % 160;
            sm[t] = g_Row[(u[i] * BSZ + r / 5) * 8 + (r % 5)];
        }
        __syncthreads();

        int i0 = s;
        float rn = 0.f;
        for (int bb = 0; bb < BSZ; bb++) rn += sm[i0 * 160 + bb * 5 + i0];
        float res = sqrtf(rn) / (1e-5f + sqrtf(g_Rden[k]));
        outslot = pw;
        if (res < TOLV || ks >= 50) break;
        if (tid < BSZ) solve_smem(tid, ks, u, sm, &sAlpha[tid * 5]);
        __syncthreads();
    }

    // ---- final: out = F[outslot] ----
    {
        const float4* src = (const float4*)g_Fp[outslot];
        for (int i4 = gt; i4 < NTOT / 4; i4 += nblk * 256) ((float4*)out)[i4] = src[i4];
    }
}

// ---------------- host ----------------
extern "C" void kernel_launch(void* const* d_in, const int* in_sizes, int n_in,
                              void* d_out, int out_size) {
    const float* x = nullptr; const float* W = nullptr;
    const float* bias = nullptr; const int* mask = nullptr;
    for (int i = 0; i < n_in; i++) {
        switch (in_sizes[i]) {
            case 4194304: x    = (const float*)d_in[i]; break;
            case 147456:  W    = (const float*)d_in[i]; break;
            case 128:     bias = (const float*)d_in[i]; break;
            case 32768:   mask = (const int*)d_in[i];   break;
        }
    }
    float* out = (float*)d_out;

    int smcount = 0;
    if (cudaDeviceGetAttribute(&smcount, cudaDevAttrMultiProcessorCount, 0) != cudaSuccess
        || smcount <= 0) smcount = 148;
    int nblk = smcount * 4;   // 4 blocks/SM (64-reg cap via launch_bounds)

    cudaFuncSetAttribute(mon_persistent, cudaFuncAttributeMaxDynamicSharedMemorySize, SMEM_TOTAL);
    mon_persistent<<<nblk, 256, SMEM_TOTAL>>>(nblk, x, mask, bias, W, out);
    (void)out_size;
}